// round 16
// baseline (speedup 1.0000x reference)
#include <cuda_runtime.h>
#include <cuda_fp16.h>
#include <cstdint>

#define HH 256
#define WW 256
#define HW 65536
#define C 64
#define O 64
#define B 16
#define NK 4
#define GROUPS 8
#define LAG 512

#define SMEM_BYTES (324 * 128)   // [px 0..323][64ch fp16] swizzled rows = 41472

// ---- scratch ----
__device__ __half g_wt[B * 9 * O * C];          // fp16 weights, fragment-ordered
__device__ uint32_t g_y[(B * O * HW) / 2];      // packed half2 y, warp-linear layout
__device__ float g_sum[B * GROUPS];
__device__ float g_sumsq[B * GROUPS];
__device__ int g_done[B];                       // per-batch conv-CTA completion count

__device__ __forceinline__ void mma_f16(float* d, const uint32_t* a,
                                        uint32_t b0, uint32_t b1) {
    asm("mma.sync.aligned.m16n8k16.row.col.f32.f16.f16.f32 "
        "{%0,%1,%2,%3}, {%4,%5,%6,%7}, {%8,%9}, {%0,%1,%2,%3};"
        : "+f"(d[0]), "+f"(d[1]), "+f"(d[2]), "+f"(d[3])
        : "r"(a[0]), "r"(a[1]), "r"(a[2]), "r"(a[3]), "r"(b0), "r"(b1));
}
__device__ __forceinline__ void ldmatrix_x4(uint32_t* r, uint32_t addr) {
    asm volatile("ldmatrix.sync.aligned.m8n8.x4.shared.b16 {%0,%1,%2,%3}, [%4];"
                 : "=r"(r[0]), "=r"(r[1]), "=r"(r[2]), "=r"(r[3]) : "r"(addr));
}
__device__ __forceinline__ uint32_t packh2(float a, float b) {
    __half2 h = __floats2half2_rn(a, b);
    return *(uint32_t*)&h;
}

// ============================================================================
// Kernel 0: softmax mix + modulate + demodulate -> fp16 fragment-ordered g_wt.
// Layout (halves): [b][tap][wo(2)][kt(4)][mt(2)][lane(32)][pos(8)]
// Also zeroes GN accumulators and completion counters.
// ============================================================================
__global__ void weight_kernel(const float* __restrict__ mod,
                              const float* __restrict__ kmod,
                              const float* __restrict__ cw) {
    int o = blockIdx.x, b = blockIdx.y, i = threadIdx.x;

    float k0 = kmod[b*NK], k1 = kmod[b*NK+1], k2 = kmod[b*NK+2], k3 = kmod[b*NK+3];
    float mx = fmaxf(fmaxf(k0, k1), fmaxf(k2, k3));
    float e0 = __expf(k0-mx), e1 = __expf(k1-mx), e2 = __expf(k2-mx), e3 = __expf(k3-mx);
    float inv = 1.0f / (e0+e1+e2+e3);
    float a0 = e0*inv, a1 = e1*inv, a2 = e2*inv, a3 = e3*inv;
    float mi = mod[b*C + i] + 1.0f;

    float wv[9], ss = 0.0f;
#pragma unroll
    for (int k = 0; k < 9; k++) {
        int base = (o*C + i)*9 + k;
        const int st = O*C*9;
        float v = a0*cw[base] + a1*cw[st+base] + a2*cw[2*st+base] + a3*cw[3*st+base];
        v *= mi;
        wv[k] = v; ss += v*v;
    }
#pragma unroll
    for (int off = 16; off; off >>= 1) ss += __shfl_xor_sync(~0u, ss, off);
    __shared__ float sh[2];
    if ((i & 31) == 0) sh[i>>5] = ss;
    __syncthreads();
    float innorm = rsqrtf(fmaxf(sh[0] + sh[1], 1e-8f));

    int wo = o >> 5, m5 = o & 31, mt = m5 >> 4, row = m5 & 15;
    int kt = i >> 4, kk = i & 15;
    int rA = ((kk >= 8) ? 2 : 0) + ((row >= 8) ? 1 : 0);
    int lane = ((row & 7) << 2) | ((kk & 7) >> 1);
    int pos = rA * 2 + (kk & 1);

#pragma unroll
    for (int k = 0; k < 9; k++) {
        long long idx = (((((long long)(b*9 + k)*2 + wo)*4 + kt)*2 + mt)*32 + lane)*8 + pos;
        g_wt[idx] = __float2half_rn(wv[k] * innorm);
    }

    if (o == 0 && i < GROUPS) { g_sum[b*GROUPS+i] = 0.0f; g_sumsq[b*GROUPS+i] = 0.0f; }
    if (o == 0 && i == 63) g_done[b] = 0;
}

// ============================================================================
// Kernel 1: FUSED conv + groupnorm. 1D grid of 4608 CTAs.
//  bid < 4096 : conv tile (b=bid>>8, by=(bid>>4)&15, bx=bid&15), then publish.
//  bid >= 512 : after spin on g_done[(bid-512)>>8]==256, normalize region
//               nt=bid-512 from warp-linear fp16 scratch -> NCHW fp32 d_out.
// Lag (512) > wave size (~296) and dispatch is bid-ordered => no deadlock,
// near-zero spin; norm DRAM traffic hides under tensor-bound conv.
// ============================================================================
__global__ void __launch_bounds__(256, 2)
conv_kernel(const float* __restrict__ x, float* __restrict__ out,
            const float* __restrict__ gamma, const float* __restrict__ beta) {
    extern __shared__ char smem[];
    __shared__ float gsum[GROUPS], gsq[GROUPS];
    int bid = blockIdx.x;
    int tid = threadIdx.x, wid = tid >> 5, lane = tid & 31;

    if (bid < 4096) {
        int b = bid >> 8;
        int h0 = ((bid >> 4) & 15) * 16, w0 = (bid & 15) * 16;
        uint32_t xsb;
        asm("{ .reg .u64 t; cvta.to.shared.u64 t, %1; cvt.u32.u64 %0, t; }"
            : "=r"(xsb) : "l"((void*)smem));

        int wo = wid & 1;            // O half
        int wn = wid >> 1;           // pixel quarter: tile rows 4*wn..4*wn+3
        int r8 = lane & 7;
        int gb = (lane >> 3) & 1;
        int mhi = lane >> 4;

        if (tid < GROUPS) { gsum[tid] = 0.0f; gsq[tid] = 0.0f; }

        // ---- stage x tile: [px][64ch] fp16, chunk-swizzled, zero padded ----
        const float* xb = x + (long long)b * C * HW;
        for (int u = tid; u < 2592; u += 256) {
            int j = u / 324;
            int px = u - j * 324;
            int rr = px / 18, cc = px - rr * 18;
            int gh = h0 + rr - 1, gw = w0 + cc - 1;
            float f[8];
            if ((unsigned)gh < HH && (unsigned)gw < WW) {
                const float* p = xb + (8 * j) * HW + gh * WW + gw;
#pragma unroll
                for (int i = 0; i < 8; i++) f[i] = p[i * HW];
            } else {
#pragma unroll
                for (int i = 0; i < 8; i++) f[i] = 0.0f;
            }
            uint32_t dst = xsb + (px << 7) + ((j ^ (px & 7)) << 4);
            asm volatile("st.shared.v4.b32 [%0], {%1,%2,%3,%4};"
                         :: "r"(dst), "r"(packh2(f[0], f[1])), "r"(packh2(f[2], f[3])),
                            "r"(packh2(f[4], f[5])), "r"(packh2(f[6], f[7])) : "memory");
        }
        __syncthreads();

        float acc[2][8][4];
#pragma unroll
        for (int mt = 0; mt < 2; mt++)
#pragma unroll
            for (int nt = 0; nt < 8; nt++)
#pragma unroll
                for (int r = 0; r < 4; r++) acc[mt][nt][r] = 0.0f;

        int px0[4];
#pragma unroll
        for (int ntp = 0; ntp < 4; ntp++) {
            int nt = 2 * ntp + mhi;
            px0[ntp] = (wn * 4 + (nt >> 1)) * 18 + (nt & 1) * 8 + r8;
        }

        const uint4* wf = (const uint4*)g_wt + ((b * 9 * 2 + wo) * 8) * 32 + lane;

#pragma unroll 1
        for (int tap = 0; tap < 9; tap++) {
            int kh = tap / 3, kw = tap - kh * 3;
            int dpx = kh * 18 + kw;
            const uint4* a_base = wf + (tap * 16) * 32;

            uint32_t pxb[4];
            int pxl[4];
#pragma unroll
            for (int ntp = 0; ntp < 4; ntp++) {
                int px = px0[ntp] + dpx;
                pxb[ntp] = xsb + (px << 7);
                pxl[ntp] = px & 7;
            }

#pragma unroll
            for (int kt = 0; kt < 4; kt++) {
                uint4 af0 = a_base[(kt * 2 + 0) * 32];
                uint4 af1 = a_base[(kt * 2 + 1) * 32];
                int cb = kt * 2 + gb;
#pragma unroll
                for (int ntp = 0; ntp < 4; ntp++) {
                    uint32_t br[4];
                    ldmatrix_x4(br, pxb[ntp] + (uint32_t)((cb ^ pxl[ntp]) << 4));
                    mma_f16(acc[0][2 * ntp],     (const uint32_t*)&af0, br[0], br[1]);
                    mma_f16(acc[1][2 * ntp],     (const uint32_t*)&af1, br[0], br[1]);
                    mma_f16(acc[0][2 * ntp + 1], (const uint32_t*)&af0, br[2], br[3]);
                    mma_f16(acc[1][2 * ntp + 1], (const uint32_t*)&af1, br[2], br[3]);
                }
            }
        }

        // ---- store y (fp16, warp-linear) + GN partial stats ----
        uint32_t* ybuf = g_y + ((long long)bid * 8 + wid) * 1024 + lane;
        float s[2][2] = {{0, 0}, {0, 0}}, s2[2][2] = {{0, 0}, {0, 0}};
#pragma unroll
        for (int mt = 0; mt < 2; mt++) {
#pragma unroll
            for (int nt = 0; nt < 8; nt++) {
                int slot = (mt * 8 + nt) * 2;
                float c0 = acc[mt][nt][0], c1 = acc[mt][nt][1];
                float c2 = acc[mt][nt][2], c3 = acc[mt][nt][3];
                ybuf[slot * 32] = packh2(c0, c1);
                ybuf[(slot + 1) * 32] = packh2(c2, c3);
                s[mt][0] += c0 + c1;  s2[mt][0] += c0 * c0 + c1 * c1;
                s[mt][1] += c2 + c3;  s2[mt][1] += c2 * c2 + c3 * c3;
            }
        }
#pragma unroll
        for (int off = 16; off; off >>= 1) {
#pragma unroll
            for (int mt = 0; mt < 2; mt++)
#pragma unroll
                for (int hi = 0; hi < 2; hi++) {
                    s[mt][hi]  += __shfl_xor_sync(~0u, s[mt][hi], off);
                    s2[mt][hi] += __shfl_xor_sync(~0u, s2[mt][hi], off);
                }
        }
        if (lane == 0) {
#pragma unroll
            for (int mt = 0; mt < 2; mt++)
#pragma unroll
                for (int hi = 0; hi < 2; hi++) {
                    int g = wo * 4 + mt * 2 + hi;
                    atomicAdd(&gsum[g], s[mt][hi]);
                    atomicAdd(&gsq[g], s2[mt][hi]);
                }
        }
        __syncthreads();
        if (tid < GROUPS) {
            atomicAdd(&g_sum[b * GROUPS + tid], gsum[tid]);
            atomicAdd(&g_sumsq[b * GROUPS + tid], gsq[tid]);
        }
        // ---- publish: all scratch stores + stat atomics visible, then count ----
        __threadfence();
        __syncthreads();
        if (tid == 0) atomicAdd(&g_done[b], 1);
    }

    // ================= norm phase: region nt = bid - LAG =================
    int nt = bid - LAG;
    if (nt < 0) return;
    int nb = nt >> 8;

    if (tid == 0) {
        volatile int* dp = (volatile int*)&g_done[nb];
        while (*dp < 256) __nanosleep(128);
    }
    __syncthreads();
    __threadfence();   // acquire: order spin observation before data reads

    const float invN = 1.0f / (8.0f * HH * WW);
    int bxn = nt & 15, byn = (nt >> 4) & 15;
    const uint4* gy4 = (const uint4*)g_y;
    int base4 = nt << 11;   // 2048 uint4 per region

#pragma unroll
    for (int it = 0; it < 8; it++) {
        int t = tid + it * 256;
        uint4 u = gy4[base4 + t];

        int g2v = t & 7;
        int sv = (t >> 3) & 31;
        int wv = (t >> 8) & 7;
        int pair = sv & 1, unit = sv >> 1, mt = unit >> 3, nt8 = unit & 7;
        int wo = wv & 1, wn = wv >> 1;

        int o = wo * 32 + mt * 16 + pair * 8 + g2v;
        int g = o >> 3;
        int gh = byn * 16 + wn * 4 + (nt8 >> 1);
        int gw = bxn * 16 + (nt8 & 1) * 8;

        float mean = g_sum[nb * GROUPS + g] * invN;
        float var = g_sumsq[nb * GROUPS + g] * invN - mean * mean;
        float istd = rsqrtf(var + 1e-5f);
        float ga = gamma[o], be = beta[o];

        float2 f0 = __half22float2(*(__half2*)&u.x);
        float2 f1 = __half22float2(*(__half2*)&u.y);
        float2 f2 = __half22float2(*(__half2*)&u.z);
        float2 f3 = __half22float2(*(__half2*)&u.w);
        float vv[8] = {f0.x, f0.y, f1.x, f1.y, f2.x, f2.y, f3.x, f3.y};
        float rr[8];
#pragma unroll
        for (int k = 0; k < 8; k++) {
            float tt = (vv[k] - mean) * istd * ga + be;
            rr[k] = tt / (1.0f + __expf(-tt));
        }
        float* dst = out + ((long long)(nb * 64 + o) * HW + gh * WW + gw);
        *(float4*)dst = make_float4(rr[0], rr[1], rr[2], rr[3]);
        *(float4*)(dst + 4) = make_float4(rr[4], rr[5], rr[6], rr[7]);
    }
}

// ============================================================================
extern "C" void kernel_launch(void* const* d_in, const int* in_sizes, int n_in,
                              void* d_out, int out_size) {
    const float* x     = (const float*)d_in[0];
    const float* mod   = (const float*)d_in[1];
    const float* kmod  = (const float*)d_in[2];
    const float* cw    = (const float*)d_in[3];
    const float* gamma = (const float*)d_in[4];
    const float* beta  = (const float*)d_in[5];
    float* out = (float*)d_out;

    cudaFuncSetAttribute(conv_kernel,
                         cudaFuncAttributeMaxDynamicSharedMemorySize, SMEM_BYTES);

    weight_kernel<<<dim3(O, B), 64>>>(mod, kmod, cw);
    conv_kernel<<<4096 + LAG, 256, SMEM_BYTES>>>(x, out, gamma, beta);
}

// round 17
// speedup vs baseline: 1.0518x; 1.0518x over previous
#include <cuda_runtime.h>
#include <cuda_fp16.h>
#include <cstdint>

#define HH 256
#define WW 256
#define HW 65536
#define C 64
#define O 64
#define B 16
#define NK 4
#define GROUPS 8

#define HALO_PX 180              // 10 rows x 18 cols
#define SMEM_BYTES (HALO_PX * 128)   // 23040

// ---- scratch ----
__device__ __half g_wt[B * 9 * O * C];          // fp16 weights, fragment-ordered
__device__ uint32_t g_y[(B * O * HW) / 2];      // packed half2 y, warp-linear layout
__device__ float g_sum[B * GROUPS];
__device__ float g_sumsq[B * GROUPS];

__device__ __forceinline__ void mma_f16(float* d, const uint32_t* a,
                                        uint32_t b0, uint32_t b1) {
    asm("mma.sync.aligned.m16n8k16.row.col.f32.f16.f16.f32 "
        "{%0,%1,%2,%3}, {%4,%5,%6,%7}, {%8,%9}, {%0,%1,%2,%3};"
        : "+f"(d[0]), "+f"(d[1]), "+f"(d[2]), "+f"(d[3])
        : "r"(a[0]), "r"(a[1]), "r"(a[2]), "r"(a[3]), "r"(b0), "r"(b1));
}
__device__ __forceinline__ void ldmatrix_x4(uint32_t* r, uint32_t addr) {
    asm volatile("ldmatrix.sync.aligned.m8n8.x4.shared.b16 {%0,%1,%2,%3}, [%4];"
                 : "=r"(r[0]), "=r"(r[1]), "=r"(r[2]), "=r"(r[3]) : "r"(addr));
}
__device__ __forceinline__ uint32_t packh2(float a, float b) {
    __half2 h = __floats2half2_rn(a, b);
    return *(uint32_t*)&h;
}

// ============================================================================
// Kernel 0: softmax mix + modulate + demodulate -> fp16 fragment-ordered g_wt.
// Layout (halves): [b][tap][wo(2)][kt(4)][mt(2)][lane(32)][pos(8)]
// ============================================================================
__global__ void weight_kernel(const float* __restrict__ mod,
                              const float* __restrict__ kmod,
                              const float* __restrict__ cw) {
    int o = blockIdx.x, b = blockIdx.y, i = threadIdx.x;

    float k0 = kmod[b*NK], k1 = kmod[b*NK+1], k2 = kmod[b*NK+2], k3 = kmod[b*NK+3];
    float mx = fmaxf(fmaxf(k0, k1), fmaxf(k2, k3));
    float e0 = __expf(k0-mx), e1 = __expf(k1-mx), e2 = __expf(k2-mx), e3 = __expf(k3-mx);
    float inv = 1.0f / (e0+e1+e2+e3);
    float a0 = e0*inv, a1 = e1*inv, a2 = e2*inv, a3 = e3*inv;
    float mi = mod[b*C + i] + 1.0f;

    float wv[9], ss = 0.0f;
#pragma unroll
    for (int k = 0; k < 9; k++) {
        int base = (o*C + i)*9 + k;
        const int st = O*C*9;
        float v = a0*cw[base] + a1*cw[st+base] + a2*cw[2*st+base] + a3*cw[3*st+base];
        v *= mi;
        wv[k] = v; ss += v*v;
    }
#pragma unroll
    for (int off = 16; off; off >>= 1) ss += __shfl_xor_sync(~0u, ss, off);
    __shared__ float sh[2];
    if ((i & 31) == 0) sh[i>>5] = ss;
    __syncthreads();
    float innorm = rsqrtf(fmaxf(sh[0] + sh[1], 1e-8f));

    int wo = o >> 5, m5 = o & 31, mt = m5 >> 4, row = m5 & 15;
    int kt = i >> 4, kk = i & 15;
    int rA = ((kk >= 8) ? 2 : 0) + ((row >= 8) ? 1 : 0);
    int lane = ((row & 7) << 2) | ((kk & 7) >> 1);
    int pos = rA * 2 + (kk & 1);

#pragma unroll
    for (int k = 0; k < 9; k++) {
        long long idx = (((((long long)(b*9 + k)*2 + wo)*4 + kt)*2 + mt)*32 + lane)*8 + pos;
        g_wt[idx] = __float2half_rn(wv[k] * innorm);
    }

    if (o == 0 && i < GROUPS) { g_sum[b*GROUPS+i] = 0.0f; g_sumsq[b*GROUPS+i] = 0.0f; }
}

// ============================================================================
// Kernel 1: fp16 tensor-core conv. CTA tile 8 rows x 16 cols (grid 16,32,16),
// halo 10x18. Warp tile 32O x 32px -> acc 32 regs -> 3 CTAs/SM (24 warps).
// B frags via ldmatrix.x4 (additive swizzle), A frags via LDG.128,
// barrier-free mainloop, warp-linear fp16 y scratch.
// ============================================================================
__global__ void __launch_bounds__(256, 3)
conv_kernel(const float* __restrict__ x) {
    extern __shared__ char smem[];
    __shared__ float gsum[GROUPS], gsq[GROUPS];
    uint32_t xsb;
    asm("{ .reg .u64 t; cvta.to.shared.u64 t, %1; cvt.u32.u64 %0, t; }"
        : "=r"(xsb) : "l"((void*)smem));

    int b = blockIdx.z;
    int h0 = blockIdx.y * 8, w0 = blockIdx.x * 16;
    int tid = threadIdx.x, wid = tid >> 5, lane = tid & 31;
    int wo = wid & 1;            // O half (32 ch)
    int wn = wid >> 1;           // row pair: tile rows 2*wn..2*wn+1
    int r8 = lane & 7;
    int gb = (lane >> 3) & 1;
    int mhi = lane >> 4;

    if (tid < GROUPS) { gsum[tid] = 0.0f; gsq[tid] = 0.0f; }

    // ---- stage x halo tile: [px(10x18)][64ch] fp16, chunk-swizzled ----
    const float* xb = x + (long long)b * C * HW;
    for (int u = tid; u < 8 * HALO_PX; u += 256) {
        int j = u / HALO_PX;          // channel chunk (8 ch)
        int px = u - j * HALO_PX;
        int rr = px / 18, cc = px - rr * 18;
        int gh = h0 + rr - 1, gw = w0 + cc - 1;
        float f[8];
        if ((unsigned)gh < HH && (unsigned)gw < WW) {
            const float* p = xb + (8 * j) * HW + gh * WW + gw;
#pragma unroll
            for (int i = 0; i < 8; i++) f[i] = p[i * HW];
        } else {
#pragma unroll
            for (int i = 0; i < 8; i++) f[i] = 0.0f;
        }
        uint32_t dst = xsb + (px << 7) + ((j ^ (px & 7)) << 4);
        asm volatile("st.shared.v4.b32 [%0], {%1,%2,%3,%4};"
                     :: "r"(dst), "r"(packh2(f[0], f[1])), "r"(packh2(f[2], f[3])),
                        "r"(packh2(f[4], f[5])), "r"(packh2(f[6], f[7])) : "memory");
    }
    __syncthreads();   // the ONLY barrier before epilogue

    float acc[2][4][4];
#pragma unroll
    for (int mt = 0; mt < 2; mt++)
#pragma unroll
        for (int nt = 0; nt < 4; nt++)
#pragma unroll
            for (int r = 0; r < 4; r++) acc[mt][nt][r] = 0.0f;

    // per-lane base pixel for each nt-pair: nt = 2*ntp + mhi
    // nt -> (row = wn*2 + (nt>>1), colhalf = nt&1)
    int px0[2];
#pragma unroll
    for (int ntp = 0; ntp < 2; ntp++) {
        int nt = 2 * ntp + mhi;
        px0[ntp] = (wn * 2 + (nt >> 1)) * 18 + (nt & 1) * 8 + r8;
    }

    // A fragment base: uint4 index = ((((b*9+tap)*2+wo)*4+kt)*2+mt)*32 + lane
    const uint4* wf = (const uint4*)g_wt + ((b * 9 * 2 + wo) * 8) * 32 + lane;

#pragma unroll 1
    for (int tap = 0; tap < 9; tap++) {
        int kh = tap / 3, kw = tap - kh * 3;
        int dpx = kh * 18 + kw;
        const uint4* a_base = wf + (tap * 16) * 32;

        uint32_t pxb[2];
        int pxl[2];
#pragma unroll
        for (int ntp = 0; ntp < 2; ntp++) {
            int px = px0[ntp] + dpx;
            pxb[ntp] = xsb + (px << 7);
            pxl[ntp] = px & 7;
        }

#pragma unroll
        for (int kt = 0; kt < 4; kt++) {
            uint4 af0 = a_base[(kt * 2 + 0) * 32];
            uint4 af1 = a_base[(kt * 2 + 1) * 32];
            int cb = kt * 2 + gb;
#pragma unroll
            for (int ntp = 0; ntp < 2; ntp++) {
                uint32_t br[4];
                ldmatrix_x4(br, pxb[ntp] + (uint32_t)((cb ^ pxl[ntp]) << 4));
                mma_f16(acc[0][2 * ntp],     (const uint32_t*)&af0, br[0], br[1]);
                mma_f16(acc[1][2 * ntp],     (const uint32_t*)&af1, br[0], br[1]);
                mma_f16(acc[0][2 * ntp + 1], (const uint32_t*)&af0, br[2], br[3]);
                mma_f16(acc[1][2 * ntp + 1], (const uint32_t*)&af1, br[2], br[3]);
            }
        }
    }

    // ---- store y (fp16, warp-linear coalesced) + GN partial stats ----
    int cta_lin = (b * 32 + blockIdx.y) * 16 + blockIdx.x;
    uint32_t* ybuf = g_y + ((long long)cta_lin * 8 + wid) * 512 + lane;
    float s[2][2] = {{0, 0}, {0, 0}}, s2[2][2] = {{0, 0}, {0, 0}};
#pragma unroll
    for (int mt = 0; mt < 2; mt++) {
#pragma unroll
        for (int nt = 0; nt < 4; nt++) {
            int slot = (mt * 4 + nt) * 2;
            float c0 = acc[mt][nt][0], c1 = acc[mt][nt][1];
            float c2 = acc[mt][nt][2], c3 = acc[mt][nt][3];
            ybuf[slot * 32] = packh2(c0, c1);
            ybuf[(slot + 1) * 32] = packh2(c2, c3);
            s[mt][0] += c0 + c1;  s2[mt][0] += c0 * c0 + c1 * c1;
            s[mt][1] += c2 + c3;  s2[mt][1] += c2 * c2 + c3 * c3;
        }
    }
#pragma unroll
    for (int off = 16; off; off >>= 1) {
#pragma unroll
        for (int mt = 0; mt < 2; mt++)
#pragma unroll
            for (int hi = 0; hi < 2; hi++) {
                s[mt][hi]  += __shfl_xor_sync(~0u, s[mt][hi], off);
                s2[mt][hi] += __shfl_xor_sync(~0u, s2[mt][hi], off);
            }
    }
    if (lane == 0) {
#pragma unroll
        for (int mt = 0; mt < 2; mt++)
#pragma unroll
            for (int hi = 0; hi < 2; hi++) {
                int g = wo * 4 + mt * 2 + hi;
                atomicAdd(&gsum[g], s[mt][hi]);
                atomicAdd(&gsq[g], s2[mt][hi]);
            }
    }
    __syncthreads();
    if (tid < GROUPS) {
        atomicAdd(&g_sum[b * GROUPS + tid], gsum[tid]);
        atomicAdd(&g_sumsq[b * GROUPS + tid], gsq[tid]);
    }
}

// ============================================================================
// Kernel 2: GroupNorm + SiLU. Reads warp-linear fp16 y (coalesced), decodes
// coordinates arithmetically, writes NCHW fp32 d_out.
// idx bits: lane[0:5) slot[5:9) wid[9:12) bx[12:16) by[16:21) b[21:25)
// ============================================================================
__global__ void norm_kernel(float* __restrict__ out,
                            const float* __restrict__ gamma,
                            const float* __restrict__ beta) {
    int idx = blockIdx.x * blockDim.x + threadIdx.x;
    uint32_t u = g_y[idx];

    int lane = idx & 31, s = (idx >> 5) & 15, wid = (idx >> 9) & 7;
    int bx = (idx >> 12) & 15, by = (idx >> 16) & 31, b = idx >> 21;
    int pair = s & 1, unit = s >> 1, mt = unit >> 2, nt = unit & 3;
    int wo = wid & 1, wn = wid >> 1, g2 = lane >> 2, qp = lane & 3;

    int o = wo * 32 + mt * 16 + pair * 8 + g2;
    int g = o >> 3;
    int gh = by * 8 + wn * 2 + (nt >> 1);
    int gw = bx * 16 + (nt & 1) * 8 + 2 * qp;

    const float invN = 1.0f / (8.0f * HH * WW);
    float mean = g_sum[b * GROUPS + g] * invN;
    float var = g_sumsq[b * GROUPS + g] * invN - mean * mean;
    float istd = rsqrtf(var + 1e-5f);
    float ga = gamma[o], be = beta[o];

    float2 f = __half22float2(*(__half2*)&u);
    float t0 = (f.x - mean) * istd * ga + be;
    float t1 = (f.y - mean) * istd * ga + be;
    float2 r;
    r.x = t0 / (1.0f + __expf(-t0));
    r.y = t1 / (1.0f + __expf(-t1));
    *(float2*)(out + ((long long)(b * 64 + o) * HW + gh * WW + gw)) = r;
}

// ============================================================================
extern "C" void kernel_launch(void* const* d_in, const int* in_sizes, int n_in,
                              void* d_out, int out_size) {
    const float* x     = (const float*)d_in[0];
    const float* mod   = (const float*)d_in[1];
    const float* kmod  = (const float*)d_in[2];
    const float* cw    = (const float*)d_in[3];
    const float* gamma = (const float*)d_in[4];
    const float* beta  = (const float*)d_in[5];
    float* out = (float*)d_out;

    cudaFuncSetAttribute(conv_kernel,
                         cudaFuncAttributeMaxDynamicSharedMemorySize, SMEM_BYTES);

    weight_kernel<<<dim3(O, B), 64>>>(mod, kmod, cw);
    conv_kernel<<<dim3(16, 32, B), 256, SMEM_BYTES>>>(x);
    norm_kernel<<<(B * O * HW / 2) / 256, 256>>>(out, gamma, beta);
}